// round 11
// baseline (speedup 1.0000x reference)
#include <cuda_runtime.h>
#include <cuda_bf16.h>

#define NN 50000
#define EE 600000
#define DD 128
#define NTILES 391            // ceil(NN/128)
#define GRID_GEMM 148
#define SCAN_BLKS 49          // ceil(NN/1024)

// ---- fused kernel smem (bytes) ----
// W hi 64KB | W lo 64KB | mean tile 2 chunks x (hi 16KB + lo 16KB) | hin chunk (hi 16KB + lo 16KB)
#define SM_WH 0
#define SM_WL 65536
#define SM_MH 131072
#define SM_HB 196608
#define FUSED_SMEM 229376     // 224 KB

// swizzles: XOR row%8 into the 16B-chunk index (conflict-free ldmatrix)
#define SWA(o) ((o) ^ ((((unsigned)(o)) >> 3) & 0x70))   // 128B rows (A chunks)
#define SWW(o) ((o) ^ ((((unsigned)(o)) >> 5) & 0x70))   // 512B rows (W tiles)

typedef unsigned int u32;

// ---------------- scratch ----------------
__device__ float g_bufA[NN * DD];
__device__ float g_bufB[NN * DD];
__device__ int   g_src[EE];
__device__ int   g_dst[EE];
__device__ int   g_col[EE];
__device__ int   g_rowptr[NN + 1];
__device__ int   g_cursor[NN];
__device__ int   g_count[NN];
__device__ float g_invdeg[NN];
__device__ int   g_btot[64];
__device__ int   g_boff[64];
__device__ int   g_is64;

// ---------------- helpers ----------------
__device__ __forceinline__ u32 smem_u32(const void* p) {
    u32 a;
    asm("{ .reg .u64 t; cvta.to.shared.u64 t, %1; cvt.u32.u64 %0, t; }" : "=r"(a) : "l"(p));
    return a;
}
__device__ __forceinline__ void ldm4(u32& r0, u32& r1, u32& r2, u32& r3, u32 a) {
    asm volatile("ldmatrix.sync.aligned.m8n8.x4.shared.b16 {%0,%1,%2,%3}, [%4];"
                 : "=r"(r0), "=r"(r1), "=r"(r2), "=r"(r3) : "r"(a));
}
__device__ __forceinline__ void mma_bf16(float* d, const u32* a, u32 b0, u32 b1) {
    asm volatile(
        "mma.sync.aligned.m16n8k16.row.col.f32.bf16.bf16.f32 "
        "{%0,%1,%2,%3}, {%4,%5,%6,%7}, {%8,%9}, {%0,%1,%2,%3};"
        : "+f"(d[0]), "+f"(d[1]), "+f"(d[2]), "+f"(d[3])
        : "r"(a[0]), "r"(a[1]), "r"(a[2]), "r"(a[3]), "r"(b0), "r"(b1));
}
__device__ __forceinline__ u32 pkbf2(float x, float y) {
    __nv_bfloat162 h = __floats2bfloat162_rn(x, y);
    return *(u32*)&h;
}
__device__ __forceinline__ void split4(float4 v, uint2& h, uint2& l) {
    float bx = __bfloat162float(__float2bfloat16_rn(v.x));
    float by = __bfloat162float(__float2bfloat16_rn(v.y));
    float bz = __bfloat162float(__float2bfloat16_rn(v.z));
    float bw = __bfloat162float(__float2bfloat16_rn(v.w));
    h.x = pkbf2(v.x, v.y);           h.y = pkbf2(v.z, v.w);
    l.x = pkbf2(v.x - bx, v.y - by); l.y = pkbf2(v.z - bz, v.w - bw);
}
#define BAR_SYNC(id)   asm volatile("bar.sync %0, %1;"   :: "r"(id), "r"(512) : "memory")
#define BAR_ARRIVE(id) asm volatile("bar.arrive %0, %1;" :: "r"(id), "r"(512) : "memory")

// ---------------- preprocessing (identical to R8 best) ----------------
__global__ void init_kernel(const unsigned long long* __restrict__ e) {
    int i = blockIdx.x * blockDim.x + threadIdx.x;
    if (i < NN) g_count[i] = 0;
    if (i == 0) {
        int ok = 1;
        #pragma unroll
        for (int t = 0; t < 8; t++)
            if (e[t] >= (unsigned long long)NN) ok = 0;
        g_is64 = ok;
    }
}

__global__ void convert_hist_kernel(const void* __restrict__ eptr) {
    int i = blockIdx.x * blockDim.x + threadIdx.x;
    if (i >= EE) return;
    int s, d;
    if (g_is64) {
        const long long* e = (const long long*)eptr;
        s = (int)e[i]; d = (int)e[EE + i];
    } else {
        const int* e = (const int*)eptr;
        s = e[i]; d = e[EE + i];
    }
    g_src[i] = s;
    g_dst[i] = d;
    atomicAdd(&g_count[d], 1);
}

__global__ void scan1_kernel() {
    __shared__ int wsum[32];
    int tid = threadIdx.x;
    int lane = tid & 31, wid = tid >> 5;
    int idx = blockIdx.x * 1024 + tid;
    int v = (idx < NN) ? g_count[idx] : 0;
    int s = v;
    #pragma unroll
    for (int o = 1; o < 32; o <<= 1) {
        int t = __shfl_up_sync(0xffffffffu, s, o);
        if (lane >= o) s += t;
    }
    if (lane == 31) wsum[wid] = s;
    __syncthreads();
    if (wid == 0) {
        int w = wsum[lane];
        #pragma unroll
        for (int o = 1; o < 32; o <<= 1) {
            int t = __shfl_up_sync(0xffffffffu, w, o);
            if (lane >= o) w += t;
        }
        wsum[lane] = w;
    }
    __syncthreads();
    int incl = s + ((wid > 0) ? wsum[wid - 1] : 0);
    if (idx < NN) g_rowptr[idx] = incl - v;
    if (tid == 1023) g_btot[blockIdx.x] = incl;
}

__global__ void scan2_kernel() {
    __shared__ int w0;
    int tid = threadIdx.x;
    int lane = tid & 31, wid = tid >> 5;
    int v = (tid < SCAN_BLKS) ? g_btot[tid] : 0;
    int s = v;
    #pragma unroll
    for (int o = 1; o < 32; o <<= 1) {
        int t = __shfl_up_sync(0xffffffffu, s, o);
        if (lane >= o) s += t;
    }
    if (wid == 0 && lane == 31) w0 = s;
    __syncthreads();
    int incl = s + (wid ? w0 : 0);
    if (tid < SCAN_BLKS) g_boff[tid] = incl - v;
    if (tid == 63) g_rowptr[NN] = incl;
}

__global__ void scan3_kernel() {
    int idx = blockIdx.x * 1024 + threadIdx.x;
    if (idx >= NN) return;
    int r = g_rowptr[idx] + g_boff[blockIdx.x];
    g_rowptr[idx] = r;
    g_cursor[idx] = r;
    g_invdeg[idx] = 1.0f / (float)max(g_count[idx], 1);
}

__global__ void fill_kernel() {
    int i = blockIdx.x * blockDim.x + threadIdx.x;
    if (i >= EE) return;
    int d = g_dst[i];
    int p = atomicAdd(&g_cursor[d], 1);
    g_col[p] = g_src[i];
}

__global__ void sortnb_kernel() {
    int n = blockIdx.x * blockDim.x + threadIdx.x;
    if (n >= NN) return;
    int b = g_rowptr[n], e = g_rowptr[n + 1];
    for (int i = b + 1; i < e; i++) {
        int v = g_col[i];
        int j = i - 1;
        while (j >= b && g_col[j] > v) { g_col[j + 1] = g_col[j]; j--; }
        g_col[j + 1] = v;
    }
}

// ---------------- consumer MMA over one 64-k chunk ----------------
// acc layout: acc[mi*8 + h2*4 + ni] for warp tile 32 rows x 64 cols.
__device__ __forceinline__ void mma_chunk(float (*acc)[4], u32 AH, u32 sb, int kc,
                                          int wr, int wc, u32 a_lane, u32 b_lane) {
    const u32 AL = AH + 16384;
    #pragma unroll
    for (int ks = 0; ks < 4; ks++) {
        u32 ah[2][4], al[2][4];
        u32 aoff = (u32)(wr * 128 + ks * 32) + a_lane;
        #pragma unroll
        for (int mi = 0; mi < 2; mi++) {
            ldm4(ah[mi][0], ah[mi][1], ah[mi][2], ah[mi][3], AH + SWA(aoff + mi * 16 * 128));
            ldm4(al[mi][0], al[mi][1], al[mi][2], al[mi][3], AL + SWA(aoff + mi * 16 * 128));
        }
        #pragma unroll
        for (int h2 = 0; h2 < 2; h2++) {
            u32 bh[2][4], blr[2][4];
            u32 boff = (u32)((wc + h2 * 32) * 512 + kc * 128 + ks * 32) + b_lane;
            #pragma unroll
            for (int g = 0; g < 2; g++) {
                ldm4(bh[g][0], bh[g][1], bh[g][2], bh[g][3], sb + SM_WH + SWW(boff + g * 16 * 512));
                ldm4(blr[g][0], blr[g][1], blr[g][2], blr[g][3], sb + SM_WL + SWW(boff + g * 16 * 512));
            }
            #pragma unroll
            for (int mi = 0; mi < 2; mi++)
                #pragma unroll
                for (int ni = 0; ni < 4; ni++) {
                    float* d = acc[mi * 8 + h2 * 4 + ni];
                    u32 bA = bh[ni >> 1][(ni & 1) * 2];
                    u32 bB = bh[ni >> 1][(ni & 1) * 2 + 1];
                    u32 lA = blr[ni >> 1][(ni & 1) * 2];
                    u32 lB = blr[ni >> 1][(ni & 1) * 2 + 1];
                    mma_bf16(d, ah[mi], bA, bB);   // hi*hi
                    mma_bf16(d, ah[mi], lA, lB);   // hi*lo
                    mma_bf16(d, al[mi], bA, bB);   // lo*hi
                }
        }
    }
}

// ---------------- fused warp-specialized SAGE layer ----------------
// out = relu(mean_nbr(hin) @ Wl^T + hin @ Wr^T + bl), A produced on the fly.
// 148 persistent CTAs x 512 thr. Warps 0-7 (producers): per 128-row tile, walk
// each sorted CSR list ONCE with float4 lanes (full 128 cols) into the mean
// smem tile (bf16 hi/lo), then stage hin 64-k chunks. Warps 8-15 (consumers):
// bf16x3 mma (hi*hi+hi*lo+lo*hi) + bias/relu/STG. Named barriers:
//  1: mean ready   2: mean consumed   3: hin chunk ready   4: hin chunk consumed
// The L2-bound gather of tile t+1 overlaps the hin MMA + epilogue of tile t.
__global__ __launch_bounds__(512, 1)
void sage_ws_kernel(const float* __restrict__ hin,
                    const float* __restrict__ Wl, const float* __restrict__ bl,
                    const float* __restrict__ Wr, float* __restrict__ out)
{
    extern __shared__ char smem[];
    const u32 sb = smem_u32(smem);
    const int tid = threadIdx.x;
    const int w = tid >> 5;
    const int lane = tid & 31;

    // ---- stage Wcat hi/lo once: rows 512B (K=256 bf16), SWW swizzle ----
    for (int s = tid; s < 128 * 64; s += 512) {
        int n = s >> 6, k4 = s & 63;
        int k = k4 * 4;
        float4 v = (k < 128) ? *(const float4*)(Wl + n * 128 + k)
                             : *(const float4*)(Wr + n * 128 + (k - 128));
        uint2 h, l;
        split4(v, h, l);
        u32 off = SWW(n * 512 + k4 * 8);
        *(uint2*)(smem + SM_WH + off) = h;
        *(uint2*)(smem + SM_WL + off) = l;
    }
    __syncthreads();

    if (w < 8) {
        // ================= producers =================
        const u32 mbase = SM_MH + (lane >> 4) * 32768;     // mean chunk for this lane's cols
        const u32 moff0 = (u32)((lane & 15) * 8);
        int mean_it = 0, hin_it = 0;
        for (int tix = blockIdx.x; tix < NTILES; tix += GRID_GEMM) {
            const int row0 = tix * 128;
            if (mean_it++) BAR_SYNC(2);                    // mean buffer free
            // ---- gather mean: warp owns rows w*16..+15, lane owns cols 4*lane..+3 ----
            const float4* p = (const float4*)hin;
            for (int i = 0; i < 16; i++) {
                int r = w * 16 + i;
                int node = row0 + r;
                float4 a4 = make_float4(0.f, 0.f, 0.f, 0.f);
                if (node < NN) {
                    int j = g_rowptr[node], end = g_rowptr[node + 1];
                    for (; j + 4 <= end; j += 4) {         // MLP 4
                        float4 v0 = p[g_col[j] * 32 + lane];
                        float4 v1 = p[g_col[j + 1] * 32 + lane];
                        float4 v2 = p[g_col[j + 2] * 32 + lane];
                        float4 v3 = p[g_col[j + 3] * 32 + lane];
                        a4.x += v0.x; a4.y += v0.y; a4.z += v0.z; a4.w += v0.w;
                        a4.x += v1.x; a4.y += v1.y; a4.z += v1.z; a4.w += v1.w;
                        a4.x += v2.x; a4.y += v2.y; a4.z += v2.z; a4.w += v2.w;
                        a4.x += v3.x; a4.y += v3.y; a4.z += v3.z; a4.w += v3.w;
                    }
                    for (; j < end; j++) {
                        float4 v0 = p[g_col[j] * 32 + lane];
                        a4.x += v0.x; a4.y += v0.y; a4.z += v0.z; a4.w += v0.w;
                    }
                    float id = g_invdeg[node];
                    a4.x *= id; a4.y *= id; a4.z *= id; a4.w *= id;
                }
                uint2 h, l;
                split4(a4, h, l);
                u32 off = SWA((u32)(r * 128) + moff0);
                *(uint2*)(smem + mbase + off) = h;
                *(uint2*)(smem + mbase + 16384 + off) = l;
            }
            BAR_ARRIVE(1);                                 // mean ready
            // ---- stage hin chunks (cols c*64..+63), single-buffered ----
            for (int c = 0; c < 2; c++) {
                if (hin_it++) BAR_SYNC(4);                 // hin buffer free
                #pragma unroll
                for (int j = 0; j < 8; j++) {
                    int s = tid + j * 256;
                    int row = s >> 4, k4 = s & 15;
                    int gr = row0 + row;
                    float4 v = make_float4(0.f, 0.f, 0.f, 0.f);
                    if (gr < NN) v = *(const float4*)(hin + gr * 128 + c * 64 + k4 * 4);
                    uint2 h, l;
                    split4(v, h, l);
                    u32 off = SWA((u32)(row * 128 + k4 * 8));
                    *(uint2*)(smem + SM_HB + off) = h;
                    *(uint2*)(smem + SM_HB + 16384 + off) = l;
                }
                BAR_ARRIVE(3);                             // hin chunk ready
            }
        }
    } else {
        // ================= consumers =================
        const int cw = w - 8;
        const int wr = (cw & 3) * 32;          // warp rows: wr..wr+31
        const int wc = (cw >> 2) * 64;         // warp cols: wc..wc+63
        const u32 a_lane = (u32)((lane & 15) * 128 + ((lane >> 4) & 1) * 16);
        const u32 b_lane = (u32)(((lane & 7) + ((lane >> 4) & 1) * 8) * 512 + ((lane >> 3) & 1) * 16);
        for (int tix = blockIdx.x; tix < NTILES; tix += GRID_GEMM) {
            const int row0 = tix * 128;
            float acc[16][4];
            #pragma unroll
            for (int i = 0; i < 16; i++)
                #pragma unroll
                for (int q = 0; q < 4; q++) acc[i][q] = 0.f;

            BAR_SYNC(1);                                   // mean ready
            mma_chunk(acc, sb + SM_MH,         sb, 0, wr, wc, a_lane, b_lane);
            mma_chunk(acc, sb + SM_MH + 32768, sb, 1, wr, wc, a_lane, b_lane);
            BAR_ARRIVE(2);                                 // mean consumed
            for (int c = 0; c < 2; c++) {
                BAR_SYNC(3);                               // hin chunk ready
                mma_chunk(acc, sb + SM_HB, sb, 2 + c, wr, wc, a_lane, b_lane);
                BAR_ARRIVE(4);                             // hin chunk consumed
            }

            // ---- epilogue: bias + relu + STG (overlaps next tile's gather) ----
            #pragma unroll
            for (int mi = 0; mi < 2; mi++) {
                int r0 = row0 + wr + mi * 16 + (lane >> 2);
                #pragma unroll
                for (int n8 = 0; n8 < 8; n8++) {
                    const float* d = acc[mi * 8 + n8];
                    int c = wc + n8 * 8 + (lane & 3) * 2;
                    float2 bb = *(const float2*)(bl + c);
                    if (r0 < NN) {
                        float2 o;
                        o.x = fmaxf(d[0] + bb.x, 0.f);
                        o.y = fmaxf(d[1] + bb.y, 0.f);
                        *(float2*)(out + (long)r0 * 128 + c) = o;
                    }
                    if (r0 + 8 < NN) {
                        float2 o;
                        o.x = fmaxf(d[2] + bb.x, 0.f);
                        o.y = fmaxf(d[3] + bb.y, 0.f);
                        *(float2*)(out + (long)(r0 + 8) * 128 + c) = o;
                    }
                }
            }
        }
    }
}

// ---------------- launch ----------------
extern "C" void kernel_launch(void* const* d_in, const int* in_sizes, int n_in,
                              void* d_out, int out_size) {
    const float* x   = (const float*)d_in[0];
    const void*  ei  = d_in[1];
    const float* Wl1 = (const float*)d_in[2];
    const float* bl1 = (const float*)d_in[3];
    const float* Wr1 = (const float*)d_in[4];
    const float* Wl2 = (const float*)d_in[5];
    const float* bl2 = (const float*)d_in[6];
    const float* Wr2 = (const float*)d_in[7];
    const float* Wl3 = (const float*)d_in[8];
    const float* bl3 = (const float*)d_in[9];
    const float* Wr3 = (const float*)d_in[10];
    float* out = (float*)d_out;

    cudaFuncSetAttribute(sage_ws_kernel, cudaFuncAttributeMaxDynamicSharedMemorySize, FUSED_SMEM);

    float *pA, *pB;
    cudaGetSymbolAddress((void**)&pA, g_bufA);
    cudaGetSymbolAddress((void**)&pB, g_bufB);

    // ---- graph preprocessing (deterministic every call) ----
    init_kernel<<<(NN + 255) / 256, 256>>>((const unsigned long long*)ei);
    convert_hist_kernel<<<(EE + 255) / 256, 256>>>(ei);
    scan1_kernel<<<SCAN_BLKS, 1024>>>();
    scan2_kernel<<<1, 64>>>();
    scan3_kernel<<<SCAN_BLKS, 1024>>>();
    fill_kernel<<<(EE + 255) / 256, 256>>>();
    sortnb_kernel<<<(NN + 127) / 128, 128>>>();

    // ---- 3 fused layers ----
    sage_ws_kernel<<<GRID_GEMM, 512, FUSED_SMEM>>>(x,  Wl1, bl1, Wr1, pA);
    sage_ws_kernel<<<GRID_GEMM, 512, FUSED_SMEM>>>(pA, Wl2, bl2, Wr2, pB);
    sage_ws_kernel<<<GRID_GEMM, 512, FUSED_SMEM>>>(pB, Wl3, bl3, Wr3, out);
}

// round 12
// speedup vs baseline: 1.3535x; 1.3535x over previous
#include <cuda_runtime.h>
#include <cuda_bf16.h>

#define NN 50000
#define EE 600000
#define DD 128
#define NTILES 391            // ceil(NN/128)
#define GRID_GEMM 148
#define SCAN_BLKS 49          // ceil(NN/1024)

// ---- fused kernel smem (bytes) ----
// W hi 64KB | W lo 64KB | A: 2 chunk bufs x (hi 16KB + lo 16KB)
#define SM_WH 0
#define SM_WL 65536
#define SM_AB 131072
#define FUSED_SMEM (131072 + 2*32768)   // 196608

// swizzles: XOR row%8 into the 16B-chunk index (conflict-free ldmatrix)
#define SWA(o) ((o) ^ ((((unsigned)(o)) >> 3) & 0x70))   // 128B rows (A chunks)
#define SWW(o) ((o) ^ ((((unsigned)(o)) >> 5) & 0x70))   // 512B rows (W tiles)

typedef unsigned int u32;

// ---------------- scratch ----------------
__device__ float g_bufA[NN * DD];
__device__ float g_bufB[NN * DD];
__device__ int   g_src[EE];
__device__ int   g_dst[EE];
__device__ int   g_col[EE];
__device__ int   g_rowptr[NN + 1];
__device__ int   g_cursor[NN];
__device__ int   g_count[NN];          // zero at load; re-zeroed by sortnb each call
__device__ float g_invdeg[NN];
__device__ int   g_btot[64];
__device__ int   g_boff[64];

// ---------------- helpers ----------------
__device__ __forceinline__ u32 smem_u32(const void* p) {
    u32 a;
    asm("{ .reg .u64 t; cvta.to.shared.u64 t, %1; cvt.u32.u64 %0, t; }" : "=r"(a) : "l"(p));
    return a;
}
__device__ __forceinline__ void ldm4(u32& r0, u32& r1, u32& r2, u32& r3, u32 a) {
    asm volatile("ldmatrix.sync.aligned.m8n8.x4.shared.b16 {%0,%1,%2,%3}, [%4];"
                 : "=r"(r0), "=r"(r1), "=r"(r2), "=r"(r3) : "r"(a));
}
__device__ __forceinline__ void mma_bf16(float* d, const u32* a, u32 b0, u32 b1) {
    asm volatile(
        "mma.sync.aligned.m16n8k16.row.col.f32.bf16.bf16.f32 "
        "{%0,%1,%2,%3}, {%4,%5,%6,%7}, {%8,%9}, {%0,%1,%2,%3};"
        : "+f"(d[0]), "+f"(d[1]), "+f"(d[2]), "+f"(d[3])
        : "r"(a[0]), "r"(a[1]), "r"(a[2]), "r"(a[3]), "r"(b0), "r"(b1));
}
__device__ __forceinline__ u32 pkbf2(float x, float y) {
    __nv_bfloat162 h = __floats2bfloat162_rn(x, y);
    return *(u32*)&h;
}
__device__ __forceinline__ void split4(float4 v, uint2& h, uint2& l) {
    float bx = __bfloat162float(__float2bfloat16_rn(v.x));
    float by = __bfloat162float(__float2bfloat16_rn(v.y));
    float bz = __bfloat162float(__float2bfloat16_rn(v.z));
    float bw = __bfloat162float(__float2bfloat16_rn(v.w));
    h.x = pkbf2(v.x, v.y);           h.y = pkbf2(v.z, v.w);
    l.x = pkbf2(v.x - bx, v.y - by); l.y = pkbf2(v.z - bz, v.w - bw);
}

// ---------------- preprocessing ----------------
// Edge convert + degree histogram. Dtype self-detect per thread: reference says
// int64 but JAX w/o x64 emits int32; an int64 view of int32 data is >= NN
// almost surely. 8 broadcast loads per thread, L1-resident.
__global__ void convert_hist_kernel(const void* __restrict__ eptr) {
    int i = blockIdx.x * blockDim.x + threadIdx.x;
    if (i >= EE) return;
    const unsigned long long* e64 = (const unsigned long long*)eptr;
    bool is64 = true;
    #pragma unroll
    for (int t = 0; t < 8; t++)
        is64 &= (e64[t] < (unsigned long long)NN);
    int s, d;
    if (is64) {
        const long long* e = (const long long*)eptr;
        s = (int)e[i]; d = (int)e[EE + i];
    } else {
        const int* e = (const int*)eptr;
        s = e[i]; d = e[EE + i];
    }
    g_src[i] = s;
    g_dst[i] = d;
    atomicAdd(&g_count[d], 1);
}

__global__ void scan1_kernel() {
    __shared__ int wsum[32];
    int tid = threadIdx.x;
    int lane = tid & 31, wid = tid >> 5;
    int idx = blockIdx.x * 1024 + tid;
    int v = (idx < NN) ? g_count[idx] : 0;
    int s = v;
    #pragma unroll
    for (int o = 1; o < 32; o <<= 1) {
        int t = __shfl_up_sync(0xffffffffu, s, o);
        if (lane >= o) s += t;
    }
    if (lane == 31) wsum[wid] = s;
    __syncthreads();
    if (wid == 0) {
        int w = wsum[lane];
        #pragma unroll
        for (int o = 1; o < 32; o <<= 1) {
            int t = __shfl_up_sync(0xffffffffu, w, o);
            if (lane >= o) w += t;
        }
        wsum[lane] = w;
    }
    __syncthreads();
    int incl = s + ((wid > 0) ? wsum[wid - 1] : 0);
    if (idx < NN) g_rowptr[idx] = incl - v;
    if (tid == 1023) g_btot[blockIdx.x] = incl;
}

__global__ void scan2_kernel() {
    __shared__ int w0;
    int tid = threadIdx.x;
    int lane = tid & 31, wid = tid >> 5;
    int v = (tid < SCAN_BLKS) ? g_btot[tid] : 0;
    int s = v;
    #pragma unroll
    for (int o = 1; o < 32; o <<= 1) {
        int t = __shfl_up_sync(0xffffffffu, s, o);
        if (lane >= o) s += t;
    }
    if (wid == 0 && lane == 31) w0 = s;
    __syncthreads();
    int incl = s + (wid ? w0 : 0);
    if (tid < SCAN_BLKS) g_boff[tid] = incl - v;
    if (tid == 63) g_rowptr[NN] = incl;
}

__global__ void scan3_kernel() {
    int idx = blockIdx.x * 1024 + threadIdx.x;
    if (idx >= NN) return;
    int r = g_rowptr[idx] + g_boff[blockIdx.x];
    g_rowptr[idx] = r;
    g_cursor[idx] = r;
    g_invdeg[idx] = 1.0f / (float)max(g_count[idx], 1);
}

__global__ void fill_kernel() {
    int i = blockIdx.x * blockDim.x + threadIdx.x;
    if (i >= EE) return;
    int d = g_dst[i];
    int p = atomicAdd(&g_cursor[d], 1);
    g_col[p] = g_src[i];
}

// Insertion-sort each adjacency list (deterministic summation order) and
// re-zero g_count for the NEXT call's histogram (it is free after scan3).
__global__ void sortnb_kernel() {
    int n = blockIdx.x * blockDim.x + threadIdx.x;
    if (n >= NN) return;
    int b = g_rowptr[n], e = g_rowptr[n + 1];
    for (int i = b + 1; i < e; i++) {
        int v = g_col[i];
        int j = i - 1;
        while (j >= b && g_col[j] > v) { g_col[j + 1] = g_col[j]; j--; }
        g_col[j + 1] = v;
    }
    g_count[n] = 0;
}

// ---------------- MMA over one 64-k chunk (identical to R8 inner) ----------------
__device__ __forceinline__ void mma_chunk(float (*acc)[4], u32 AH, u32 BH, u32 BL,
                                          int kc, int wr, int wc, u32 a_lane, u32 b_lane) {
    const u32 AL = AH + 16384;
    #pragma unroll
    for (int ks = 0; ks < 4; ks++) {
        u32 ah[2][4], al[2][4], bh[2][4], blr[2][4];
        u32 aoff = (u32)(wr * 128 + ks * 32) + a_lane;
        #pragma unroll
        for (int mi = 0; mi < 2; mi++)
            ldm4(ah[mi][0], ah[mi][1], ah[mi][2], ah[mi][3], AH + SWA(aoff + mi * 16 * 128));
        u32 boff = (u32)(wc * 512) + (u32)((kc * 8 + ks * 2) * 16) + b_lane;
        #pragma unroll
        for (int g = 0; g < 2; g++)
            ldm4(bh[g][0], bh[g][1], bh[g][2], bh[g][3], BH + SWW(boff + g * 16 * 512));
        #pragma unroll
        for (int mi = 0; mi < 2; mi++)
            #pragma unroll
            for (int ni = 0; ni < 4; ni++)
                mma_bf16(acc[mi * 4 + ni], ah[mi],
                         bh[ni >> 1][(ni & 1) * 2], bh[ni >> 1][(ni & 1) * 2 + 1]);
        #pragma unroll
        for (int g = 0; g < 2; g++)
            ldm4(blr[g][0], blr[g][1], blr[g][2], blr[g][3], BL + SWW(boff + g * 16 * 512));
        #pragma unroll
        for (int mi = 0; mi < 2; mi++)
            #pragma unroll
            for (int ni = 0; ni < 4; ni++)
                mma_bf16(acc[mi * 4 + ni], ah[mi],
                         blr[ni >> 1][(ni & 1) * 2], blr[ni >> 1][(ni & 1) * 2 + 1]);
        #pragma unroll
        for (int mi = 0; mi < 2; mi++)
            ldm4(al[mi][0], al[mi][1], al[mi][2], al[mi][3], AL + SWA(aoff + mi * 16 * 128));
        #pragma unroll
        for (int mi = 0; mi < 2; mi++)
            #pragma unroll
            for (int ni = 0; ni < 4; ni++)
                mma_bf16(acc[mi * 4 + ni], al[mi],
                         bh[ni >> 1][(ni & 1) * 2], bh[ni >> 1][(ni & 1) * 2 + 1]);
    }
}

// ---------------- fused SAGE layer: in-CTA aggregation + GEMM ----------------
// out = relu(mean_nbr(hin) @ Wl^T + hin @ Wr^T + bl).
// 148 persistent CTAs x 512 thr, W hi/lo staged ONCE. Per 128-row tile:
//   phase A: ALL 16 warps gather+mean the tile's rows (warp-per-row, float4
//            lanes, single CSR walk) splitting bf16 hi/lo straight into the two
//            A chunk buffers — mean never touches gmem, no extra launch.
//   phase B: R8's mma pipeline: mean chunks (kc 0,1) from smem, hin chunks
//            (kc 2,3) staged with LDG prefetch overlapping the mma.
__global__ __launch_bounds__(512, 1)
void sage_fused_kernel(const float* __restrict__ hin,
                       const float* __restrict__ Wl, const float* __restrict__ bl,
                       const float* __restrict__ Wr, float* __restrict__ out)
{
    extern __shared__ char smem[];
    const u32 sb = smem_u32(smem);
    const int tid = threadIdx.x;
    const int w = tid >> 5;
    const int lane = tid & 31;

    // ---- stage Wcat hi/lo once: rows 512B (K=256 bf16), SWW swizzle ----
    for (int s = tid; s < 128 * 64; s += 512) {
        int n = s >> 6, k4 = s & 63;
        int k = k4 * 4;
        float4 v = (k < 128) ? *(const float4*)(Wl + n * 128 + k)
                             : *(const float4*)(Wr + n * 128 + (k - 128));
        uint2 h, l;
        split4(v, h, l);
        u32 off = SWW(n * 512 + k4 * 8);
        *(uint2*)(smem + SM_WH + off) = h;
        *(uint2*)(smem + SM_WL + off) = l;
    }

    const int wr = (w & 3) * 32;           // warp row base in tile
    const int wc = (w >> 2) * 32;          // warp col base
    const u32 a_lane = (u32)((lane & 15) * 128 + ((lane >> 4) & 1) * 16);
    const u32 b_lane = (u32)(((lane & 7) + ((lane >> 4) & 1) * 8) * 512 + ((lane >> 3) & 1) * 16);
    const u32 BH = sb + SM_WH, BL = sb + SM_WL;

    float2 brg[4];
    #pragma unroll
    for (int ni = 0; ni < 4; ni++)
        brg[ni] = *(const float2*)(bl + wc + ni * 8 + (lane & 3) * 2);

    __syncthreads();

    for (int tix = blockIdx.x; tix < NTILES; tix += GRID_GEMM) {
        const int row0 = tix * 128;

        // ---- phase A: gather + mean straight into A smem (both chunk bufs) ----
        {
            const float4* p = (const float4*)hin;
            char* base = smem + SM_AB + (lane >> 4) * 32768;   // chunk buf by col half
            const u32 moff = (u32)((lane & 15) * 8);
            for (int i = 0; i < 8; i++) {
                int r = w * 8 + i;
                int node = row0 + r;
                float4 a4 = make_float4(0.f, 0.f, 0.f, 0.f);
                if (node < NN) {
                    int j = g_rowptr[node], end = g_rowptr[node + 1];
                    for (; j + 4 <= end; j += 4) {             // MLP 4
                        float4 v0 = p[g_col[j] * 32 + lane];
                        float4 v1 = p[g_col[j + 1] * 32 + lane];
                        float4 v2 = p[g_col[j + 2] * 32 + lane];
                        float4 v3 = p[g_col[j + 3] * 32 + lane];
                        a4.x += v0.x; a4.y += v0.y; a4.z += v0.z; a4.w += v0.w;
                        a4.x += v1.x; a4.y += v1.y; a4.z += v1.z; a4.w += v1.w;
                        a4.x += v2.x; a4.y += v2.y; a4.z += v2.z; a4.w += v2.w;
                        a4.x += v3.x; a4.y += v3.y; a4.z += v3.z; a4.w += v3.w;
                    }
                    for (; j < end; j++) {
                        float4 v0 = p[g_col[j] * 32 + lane];
                        a4.x += v0.x; a4.y += v0.y; a4.z += v0.z; a4.w += v0.w;
                    }
                    float id = g_invdeg[node];
                    a4.x *= id; a4.y *= id; a4.z *= id; a4.w *= id;
                }
                uint2 h, l;
                split4(a4, h, l);
                u32 off = SWA((u32)(r * 128) + moff);
                *(uint2*)(base + off) = h;
                *(uint2*)(base + 16384 + off) = l;
            }
        }
        __syncthreads();

        // ---- phase B: mma ----
        float acc[8][4];
        #pragma unroll
        for (int i = 0; i < 8; i++)
            #pragma unroll
            for (int q = 0; q < 4; q++) acc[i][q] = 0.f;

        // prefetch hin chunk 2 (cols 0..63) while mean chunks run
        float4 v[4];
        #pragma unroll
        for (int j = 0; j < 4; j++) {
            int s = tid + j * 512;
            int row = s >> 4, k4 = s & 15;
            int gr = row0 + row;
            v[j] = make_float4(0.f, 0.f, 0.f, 0.f);
            if (gr < NN) v[j] = *(const float4*)(hin + gr * 128 + k4 * 4);
        }

        mma_chunk(acc, sb + SM_AB,         BH, BL, 0, wr, wc, a_lane, b_lane);
        mma_chunk(acc, sb + SM_AB + 32768, BH, BL, 1, wr, wc, a_lane, b_lane);
        __syncthreads();   // mean bufs consumed

        // store chunk 2 into buf0; prefetch chunk 3 (cols 64..127)
        #pragma unroll
        for (int j = 0; j < 4; j++) {
            int s = tid + j * 512;
            int row = s >> 4, k4 = s & 15;
            uint2 h, l;
            split4(v[j], h, l);
            u32 off = SWA(row * 128 + k4 * 8);
            *(uint2*)(smem + SM_AB + off) = h;
            *(uint2*)(smem + SM_AB + 16384 + off) = l;
        }
        #pragma unroll
        for (int j = 0; j < 4; j++) {
            int s = tid + j * 512;
            int row = s >> 4, k4 = s & 15;
            int gr = row0 + row;
            v[j] = make_float4(0.f, 0.f, 0.f, 0.f);
            if (gr < NN) v[j] = *(const float4*)(hin + gr * 128 + 64 + k4 * 4);
        }
        __syncthreads();   // buf0 ready
        mma_chunk(acc, sb + SM_AB, BH, BL, 2, wr, wc, a_lane, b_lane);

        // store chunk 3 into buf1 (already consumed in mean phase)
        #pragma unroll
        for (int j = 0; j < 4; j++) {
            int s = tid + j * 512;
            int row = s >> 4, k4 = s & 15;
            uint2 h, l;
            split4(v[j], h, l);
            u32 off = SWA(row * 128 + k4 * 8);
            *(uint2*)(smem + SM_AB + 32768 + off) = h;
            *(uint2*)(smem + SM_AB + 32768 + 16384 + off) = l;
        }
        __syncthreads();   // buf1 ready
        mma_chunk(acc, sb + SM_AB + 32768, BH, BL, 3, wr, wc, a_lane, b_lane);
        __syncthreads();   // all bufs consumed before next tile's phase A

        // ---- epilogue: bias + relu + direct STG ----
        #pragma unroll
        for (int mi = 0; mi < 2; mi++) {
            int r0 = row0 + wr + mi * 16 + (lane >> 2);
            #pragma unroll
            for (int ni = 0; ni < 4; ni++) {
                const float* d = acc[mi * 4 + ni];
                int c = wc + ni * 8 + (lane & 3) * 2;
                if (r0 < NN) {
                    float2 o;
                    o.x = fmaxf(d[0] + brg[ni].x, 0.f);
                    o.y = fmaxf(d[1] + brg[ni].y, 0.f);
                    *(float2*)(out + (long)r0 * 128 + c) = o;
                }
                if (r0 + 8 < NN) {
                    float2 o;
                    o.x = fmaxf(d[2] + brg[ni].x, 0.f);
                    o.y = fmaxf(d[3] + brg[ni].y, 0.f);
                    *(float2*)(out + (long)(r0 + 8) * 128 + c) = o;
                }
            }
        }
    }
}

// ---------------- launch ----------------
extern "C" void kernel_launch(void* const* d_in, const int* in_sizes, int n_in,
                              void* d_out, int out_size) {
    const float* x   = (const float*)d_in[0];
    const void*  ei  = d_in[1];
    const float* Wl1 = (const float*)d_in[2];
    const float* bl1 = (const float*)d_in[3];
    const float* Wr1 = (const float*)d_in[4];
    const float* Wl2 = (const float*)d_in[5];
    const float* bl2 = (const float*)d_in[6];
    const float* Wr2 = (const float*)d_in[7];
    const float* Wl3 = (const float*)d_in[8];
    const float* bl3 = (const float*)d_in[9];
    const float* Wr3 = (const float*)d_in[10];
    float* out = (float*)d_out;

    cudaFuncSetAttribute(sage_fused_kernel, cudaFuncAttributeMaxDynamicSharedMemorySize, FUSED_SMEM);

    float *pA, *pB;
    cudaGetSymbolAddress((void**)&pA, g_bufA);
    cudaGetSymbolAddress((void**)&pB, g_bufB);

    // ---- graph preprocessing (6 launches; deterministic every call) ----
    convert_hist_kernel<<<(EE + 255) / 256, 256>>>(ei);
    scan1_kernel<<<SCAN_BLKS, 1024>>>();
    scan2_kernel<<<1, 64>>>();
    scan3_kernel<<<SCAN_BLKS, 1024>>>();
    fill_kernel<<<(EE + 255) / 256, 256>>>();
    sortnb_kernel<<<(NN + 127) / 128, 128>>>();

    // ---- 3 fused layers ----
    sage_fused_kernel<<<GRID_GEMM, 512, FUSED_SMEM>>>(x,  Wl1, bl1, Wr1, pA);
    sage_fused_kernel<<<GRID_GEMM, 512, FUSED_SMEM>>>(pA, Wl2, bl2, Wr2, pB);
    sage_fused_kernel<<<GRID_GEMM, 512, FUSED_SMEM>>>(pB, Wl3, bl3, Wr3, out);
}

// round 13
// speedup vs baseline: 1.6152x; 1.1934x over previous
#include <cuda_runtime.h>
#include <cuda_bf16.h>
#include <cuda_fp16.h>

#define NN 50000
#define EE 600000
#define DD 128
#define NTILES 391            // ceil(NN/128)
#define GRID_GEMM 148

// ---- gemm smem layout (bytes) ----
// W (fp16): [128 n][256 k] = 64KB ; A: 2 bufs x (hi 16KB + lo 16KB), fp16
#define SM_WH 0
#define SM_AB 65536
#define GEMM_SMEM (65536 + 2*32768)    // 131072

// swizzles: XOR row%8 into the 16B-chunk index (conflict-free ldmatrix)
#define SWA(o) ((o) ^ ((((unsigned)(o)) >> 3) & 0x70))   // 128B rows (A tiles)
#define SWW(o) ((o) ^ ((((unsigned)(o)) >> 5) & 0x70))   // 512B rows (W tiles)

typedef unsigned int u32;

// ---------------- scratch ----------------
__device__ float g_bufA[NN * DD];
__device__ float g_bufB[NN * DD];
__device__ float g_mean[NN * DD];
__device__ int   g_src[EE];
__device__ int   g_dst[EE];
__device__ int   g_col[EE];
__device__ int   g_rowptr[NN + 1];
__device__ int   g_cursor[NN];
__device__ int   g_count[NN];          // zero at load; re-zeroed by sortnb each call
__device__ float g_invdeg[NN];

// ---------------- helpers ----------------
__device__ __forceinline__ u32 smem_u32(const void* p) {
    u32 a;
    asm("{ .reg .u64 t; cvta.to.shared.u64 t, %1; cvt.u32.u64 %0, t; }" : "=r"(a) : "l"(p));
    return a;
}
__device__ __forceinline__ void ldm4(u32& r0, u32& r1, u32& r2, u32& r3, u32 a) {
    asm volatile("ldmatrix.sync.aligned.m8n8.x4.shared.b16 {%0,%1,%2,%3}, [%4];"
                 : "=r"(r0), "=r"(r1), "=r"(r2), "=r"(r3) : "r"(a));
}
__device__ __forceinline__ void mma_f16(float* d, const u32* a, u32 b0, u32 b1) {
    asm volatile(
        "mma.sync.aligned.m16n8k16.row.col.f32.f16.f16.f32 "
        "{%0,%1,%2,%3}, {%4,%5,%6,%7}, {%8,%9}, {%0,%1,%2,%3};"
        : "+f"(d[0]), "+f"(d[1]), "+f"(d[2]), "+f"(d[3])
        : "r"(a[0]), "r"(a[1]), "r"(a[2]), "r"(a[3]), "r"(b0), "r"(b1));
}
__device__ __forceinline__ u32 pkh2(float x, float y) {
    __half2 h = __floats2half2_rn(x, y);
    return *(u32*)&h;
}
// split float4 -> packed fp16 hi (2x u32) and fp16 lo residual (2x u32)
__device__ __forceinline__ void split4h(float4 v, uint2& h, uint2& l) {
    float hx = __half2float(__float2half_rn(v.x));
    float hy = __half2float(__float2half_rn(v.y));
    float hz = __half2float(__float2half_rn(v.z));
    float hw = __half2float(__float2half_rn(v.w));
    h.x = pkh2(v.x, v.y);            h.y = pkh2(v.z, v.w);
    l.x = pkh2(v.x - hx, v.y - hy);  l.y = pkh2(v.z - hz, v.w - hw);
}

// ---------------- preprocessing (4 launches) ----------------
// Edge convert + degree histogram. Per-thread dtype detect: reference says
// int64 but JAX w/o x64 emits int32; an int64 view of int32 data is >= NN
// almost surely (8 broadcast loads, L1-resident).
__global__ void convert_hist_kernel(const void* __restrict__ eptr) {
    int i = blockIdx.x * blockDim.x + threadIdx.x;
    if (i >= EE) return;
    const unsigned long long* e64 = (const unsigned long long*)eptr;
    bool is64 = true;
    #pragma unroll
    for (int t = 0; t < 8; t++)
        is64 &= (e64[t] < (unsigned long long)NN);
    int s, d;
    if (is64) {
        const long long* e = (const long long*)eptr;
        s = (int)e[i]; d = (int)e[EE + i];
    } else {
        const int* e = (const int*)eptr;
        s = e[i]; d = e[EE + i];
    }
    g_src[i] = s;
    g_dst[i] = d;
    atomicAdd(&g_count[d], 1);
}

// Single-block exclusive scan over g_count -> g_rowptr / g_cursor, plus inv-degree.
__global__ void scan_kernel() {
    __shared__ int wsum[32];
    __shared__ int carry_s;
    int tid = threadIdx.x;
    int lane = tid & 31, wid = tid >> 5;
    if (tid == 0) carry_s = 0;
    __syncthreads();
    for (int base = 0; base < NN; base += 1024) {
        int idx = base + tid;
        int v = (idx < NN) ? g_count[idx] : 0;
        int s = v;
        #pragma unroll
        for (int o = 1; o < 32; o <<= 1) {
            int t = __shfl_up_sync(0xffffffffu, s, o);
            if (lane >= o) s += t;
        }
        if (lane == 31) wsum[wid] = s;
        __syncthreads();
        if (wid == 0) {
            int w = wsum[lane];
            #pragma unroll
            for (int o = 1; o < 32; o <<= 1) {
                int t = __shfl_up_sync(0xffffffffu, w, o);
                if (lane >= o) w += t;
            }
            wsum[lane] = w;
        }
        __syncthreads();
        int offset = ((wid > 0) ? wsum[wid - 1] : 0) + carry_s;
        int incl = s + offset;
        if (idx < NN) {
            int excl = incl - v;
            g_rowptr[idx] = excl;
            g_cursor[idx] = excl;
            g_invdeg[idx] = 1.0f / (float)max(v, 1);
        }
        __syncthreads();
        if (tid == 1023) carry_s = incl;
        __syncthreads();
    }
    if (tid == 0) g_rowptr[NN] = carry_s;
}

__global__ void fill_kernel() {
    int i = blockIdx.x * blockDim.x + threadIdx.x;
    if (i >= EE) return;
    int d = g_dst[i];
    int p = atomicAdd(&g_cursor[d], 1);
    g_col[p] = g_src[i];
}

// Insertion-sort each adjacency list (deterministic summation order across
// calls) and re-zero g_count for the NEXT call's histogram.
__global__ void sortnb_kernel() {
    int n = blockIdx.x * blockDim.x + threadIdx.x;
    if (n >= NN) return;
    int b = g_rowptr[n], e = g_rowptr[n + 1];
    for (int i = b + 1; i < e; i++) {
        int v = g_col[i];
        int j = i - 1;
        while (j >= b && g_col[j] > v) { g_col[j + 1] = g_col[j]; j--; }
        g_col[j + 1] = v;
    }
    g_count[n] = 0;
}

// ---------------- aggregation ----------------
// One warp per node; lane owns a float4. 25.6 MB table is L2-resident.
__global__ void aggregate_kernel(const float* __restrict__ hin, float* __restrict__ mean) {
    int node = (blockIdx.x * blockDim.x + threadIdx.x) >> 5;
    if (node >= NN) return;
    int lane = threadIdx.x & 31;
    int j = g_rowptr[node], end = g_rowptr[node + 1];
    const float4* p = (const float4*)hin;
    float4 acc = make_float4(0.f, 0.f, 0.f, 0.f);
    for (; j + 2 <= end; j += 2) {
        int s0 = g_col[j], s1 = g_col[j + 1];
        float4 v0 = p[s0 * 32 + lane];
        float4 v1 = p[s1 * 32 + lane];
        acc.x += v0.x; acc.y += v0.y; acc.z += v0.z; acc.w += v0.w;
        acc.x += v1.x; acc.y += v1.y; acc.z += v1.z; acc.w += v1.w;
    }
    if (j < end) {
        float4 v = p[g_col[j] * 32 + lane];
        acc.x += v.x; acc.y += v.y; acc.z += v.z; acc.w += v.w;
    }
    float id = g_invdeg[node];
    acc.x *= id; acc.y *= id; acc.z *= id; acc.w *= id;
    *((float4*)mean + node * 32 + lane) = acc;
}

// ---------------- fp16x2 mma.sync GEMM ----------------
// out = relu([mean|h] @ [Wl;Wr]^T + bl) as one K=256 GEMM.
// W in plain fp16 (uniform weights in [-1/sqrt(128),1/sqrt(128)] round to fp16
// with ~1.2e-4 relative error); A split fp16 hi + fp16 lo residual (2^-22).
// 2 MMAs per k-step (a_hi*w + a_lo*w) instead of bf16x3's 3 — 33% less tensor
// and LDSM work. 148 persistent CTAs x 512 thr; warp tile 32x32; A chunks
// (128 rows x 64 k) double-buffered with gmem prefetch before mma.
__global__ __launch_bounds__(512, 1)
void gemm_mma_kernel(const float* __restrict__ mean, const float* __restrict__ hin,
                     const float* __restrict__ Wl, const float* __restrict__ bl,
                     const float* __restrict__ Wr, float* __restrict__ out)
{
    extern __shared__ char smem[];
    const u32 sb = smem_u32(smem);
    const int tid = threadIdx.x;
    const int w = tid >> 5;
    const int lane = tid & 31;

    // ---- stage W fp16: Wcat[n][k] (k<128: Wl, else Wr), rows 512B, SWW swizzle ----
    for (int s = tid; s < 128 * 64; s += 512) {
        int n = s >> 6, k4 = s & 63;
        int k = k4 * 4;
        float4 v = (k < 128) ? *(const float4*)(Wl + n * 128 + k)
                             : *(const float4*)(Wr + n * 128 + (k - 128));
        uint2 h;
        h.x = pkh2(v.x, v.y);
        h.y = pkh2(v.z, v.w);
        *(uint2*)(smem + SM_WH + SWW(n * 512 + k4 * 8)) = h;
    }

    // warp grid: 4 row groups x 4 col groups
    const int wr = (w & 3) * 32;           // warp row base in tile
    const int wc = (w >> 2) * 32;          // warp col base
    const u32 a_lane = (u32)((lane & 15) * 128 + ((lane >> 4) & 1) * 16);
    const u32 b_lane = (u32)(((lane & 7) + ((lane >> 4) & 1) * 8) * 512 + ((lane >> 3) & 1) * 16);

    // bias regs for this thread's columns
    float2 brg[4];
    #pragma unroll
    for (int ni = 0; ni < 4; ni++)
        brg[ni] = *(const float2*)(bl + wc + ni * 8 + (lane & 3) * 2);

    __syncthreads();

    for (int tix = blockIdx.x; tix < NTILES; tix += GRID_GEMM) {
        const int row0 = tix * 128;
        float acc[8][4];
        #pragma unroll
        for (int i = 0; i < 8; i++)
            #pragma unroll
            for (int q = 0; q < 4; q++) acc[i][q] = 0.f;

        // stage chunk 0 into buf 0
        float4 v[4];
        {
            #pragma unroll
            for (int j = 0; j < 4; j++) {
                int s = tid + j * 512;
                int row = s >> 4, k4 = s & 15;
                int gr = row0 + row;
                v[j] = make_float4(0.f, 0.f, 0.f, 0.f);
                if (gr < NN) v[j] = *(const float4*)(mean + gr * 128 + k4 * 4);
            }
            #pragma unroll
            for (int j = 0; j < 4; j++) {
                int s = tid + j * 512;
                int row = s >> 4, k4 = s & 15;
                uint2 h, l;
                split4h(v[j], h, l);
                u32 off = SWA(row * 128 + k4 * 8);
                *(uint2*)(smem + SM_AB + off) = h;
                *(uint2*)(smem + SM_AB + 16384 + off) = l;
            }
        }
        __syncthreads();

        for (int kc = 0; kc < 4; kc++) {
            const int buf = kc & 1;

            // prefetch next chunk's gmem into regs (hidden behind mma)
            if (kc < 3) {
                const float* src = (kc + 1 < 2) ? mean : hin;
                int kbase = ((kc + 1) & 1) * 64;
                #pragma unroll
                for (int j = 0; j < 4; j++) {
                    int s = tid + j * 512;
                    int row = s >> 4, k4 = s & 15;
                    int gr = row0 + row;
                    v[j] = make_float4(0.f, 0.f, 0.f, 0.f);
                    if (gr < NN) v[j] = *(const float4*)(src + gr * 128 + kbase + k4 * 4);
                }
            }

            // ---- mma over 4 k16 steps, 2 split terms ----
            const u32 AH = sb + SM_AB + buf * 32768;
            const u32 AL = AH + 16384;
            const u32 BH = sb + SM_WH;
            #pragma unroll
            for (int ks = 0; ks < 4; ks++) {
                u32 ah[2][4], al[2][4], bh[2][4];
                u32 aoff = (u32)(wr * 128) + (u32)(ks * 32) + a_lane;
                #pragma unroll
                for (int mi = 0; mi < 2; mi++) {
                    ldm4(ah[mi][0], ah[mi][1], ah[mi][2], ah[mi][3],
                         AH + SWA(aoff + mi * 16 * 128));
                    ldm4(al[mi][0], al[mi][1], al[mi][2], al[mi][3],
                         AL + SWA(aoff + mi * 16 * 128));
                }
                u32 boff = (u32)(wc * 512) + (u32)((kc * 8 + ks * 2) * 16) + b_lane;
                #pragma unroll
                for (int g = 0; g < 2; g++)
                    ldm4(bh[g][0], bh[g][1], bh[g][2], bh[g][3],
                         BH + SWW(boff + g * 16 * 512));
                // hi*w
                #pragma unroll
                for (int mi = 0; mi < 2; mi++)
                    #pragma unroll
                    for (int ni = 0; ni < 4; ni++)
                        mma_f16(acc[mi * 4 + ni], ah[mi],
                                bh[ni >> 1][(ni & 1) * 2], bh[ni >> 1][(ni & 1) * 2 + 1]);
                // lo*w
                #pragma unroll
                for (int mi = 0; mi < 2; mi++)
                    #pragma unroll
                    for (int ni = 0; ni < 4; ni++)
                        mma_f16(acc[mi * 4 + ni], al[mi],
                                bh[ni >> 1][(ni & 1) * 2], bh[ni >> 1][(ni & 1) * 2 + 1]);
            }

            // store prefetched chunk into other buffer
            if (kc < 3) {
                int nb = buf ^ 1;
                #pragma unroll
                for (int j = 0; j < 4; j++) {
                    int s = tid + j * 512;
                    int row = s >> 4, k4 = s & 15;
                    uint2 h, l;
                    split4h(v[j], h, l);
                    u32 off = SWA(row * 128 + k4 * 8);
                    *(uint2*)(smem + SM_AB + nb * 32768 + off) = h;
                    *(uint2*)(smem + SM_AB + nb * 32768 + 16384 + off) = l;
                }
            }
            __syncthreads();
        }

        // ---- epilogue: bias + relu + direct STG ----
        #pragma unroll
        for (int mi = 0; mi < 2; mi++) {
            int r0 = row0 + wr + mi * 16 + (lane >> 2);
            #pragma unroll
            for (int ni = 0; ni < 4; ni++) {
                const float* d = acc[mi * 4 + ni];
                int c = wc + ni * 8 + (lane & 3) * 2;
                if (r0 < NN) {
                    float2 o;
                    o.x = fmaxf(d[0] + brg[ni].x, 0.f);
                    o.y = fmaxf(d[1] + brg[ni].y, 0.f);
                    *(float2*)(out + (long)r0 * 128 + c) = o;
                }
                if (r0 + 8 < NN) {
                    float2 o;
                    o.x = fmaxf(d[2] + brg[ni].x, 0.f);
                    o.y = fmaxf(d[3] + brg[ni].y, 0.f);
                    *(float2*)(out + (long)(r0 + 8) * 128 + c) = o;
                }
            }
        }
        __syncthreads();   // tile done before next chunk0 staging overwrites buf0
    }
}

// ---------------- launch ----------------
extern "C" void kernel_launch(void* const* d_in, const int* in_sizes, int n_in,
                              void* d_out, int out_size) {
    const float* x   = (const float*)d_in[0];
    const void*  ei  = d_in[1];
    const float* Wl1 = (const float*)d_in[2];
    const float* bl1 = (const float*)d_in[3];
    const float* Wr1 = (const float*)d_in[4];
    const float* Wl2 = (const float*)d_in[5];
    const float* bl2 = (const float*)d_in[6];
    const float* Wr2 = (const float*)d_in[7];
    const float* Wl3 = (const float*)d_in[8];
    const float* bl3 = (const float*)d_in[9];
    const float* Wr3 = (const float*)d_in[10];
    float* out = (float*)d_out;

    cudaFuncSetAttribute(gemm_mma_kernel, cudaFuncAttributeMaxDynamicSharedMemorySize, GEMM_SMEM);

    float *pA, *pB, *pM;
    cudaGetSymbolAddress((void**)&pA, g_bufA);
    cudaGetSymbolAddress((void**)&pB, g_bufB);
    cudaGetSymbolAddress((void**)&pM, g_mean);

    // ---- graph preprocessing (4 launches; deterministic every call) ----
    convert_hist_kernel<<<(EE + 255) / 256, 256>>>(ei);      // launch 1
    scan_kernel<<<1, 1024>>>();                              // launch 2
    fill_kernel<<<(EE + 255) / 256, 256>>>();                // launch 3
    sortnb_kernel<<<(NN + 127) / 128, 128>>>();              // launch 4

    const int agg_blocks = (NN * 32 + 255) / 256;

    // ---- layer 1 ----
    aggregate_kernel<<<agg_blocks, 256>>>(x, pM);            // launch 5
    gemm_mma_kernel<<<GRID_GEMM, 512, GEMM_SMEM>>>(pM, x, Wl1, bl1, Wr1, pA);  // launch 6 (ncu)
    // ---- layer 2 ----
    aggregate_kernel<<<agg_blocks, 256>>>(pA, pM);
    gemm_mma_kernel<<<GRID_GEMM, 512, GEMM_SMEM>>>(pM, pA, Wl2, bl2, Wr2, pB);
    // ---- layer 3 ----
    aggregate_kernel<<<agg_blocks, 256>>>(pB, pM);
    gemm_mma_kernel<<<GRID_GEMM, 512, GEMM_SMEM>>>(pM, pB, Wl3, bl3, Wr3, out);
}

// round 14
// speedup vs baseline: 2.0781x; 1.2866x over previous
#include <cuda_runtime.h>
#include <cuda_bf16.h>
#include <cuda_fp16.h>

#define NN 50000
#define EE 600000
#define DD 128
#define NTILES 391            // ceil(NN/128)
#define GRID_GEMM 148
#define SCAN_BLKS 49          // ceil(NN/1024)

// ---- gemm smem layout (bytes) ----
// W (fp16): [128 n][256 k] = 64KB ; A: 2 bufs x (hi 16KB + lo 16KB), fp16
#define SM_WH 0
#define SM_AB 65536
#define GEMM_SMEM (65536 + 2*32768)    // 131072

// swizzles: XOR row%8 into the 16B-chunk index (conflict-free ldmatrix)
#define SWA(o) ((o) ^ ((((unsigned)(o)) >> 3) & 0x70))   // 128B rows (A tiles)
#define SWW(o) ((o) ^ ((((unsigned)(o)) >> 5) & 0x70))   // 512B rows (W tiles)

typedef unsigned int u32;

// ---------------- scratch ----------------
__device__ float g_bufA[NN * DD];
__device__ float g_bufB[NN * DD];
__device__ float g_mean[NN * DD];
__device__ int   g_src[EE];
__device__ int   g_dst[EE];
__device__ int   g_col[EE];
__device__ int   g_rowptr[NN + 1];
__device__ int   g_cursor[NN];
__device__ int   g_count[NN];          // zero at load; re-zeroed by sortnb each call
__device__ float g_invdeg[NN];
__device__ int   g_btot[64];
__device__ int   g_boff[64];

// ---------------- helpers ----------------
__device__ __forceinline__ u32 smem_u32(const void* p) {
    u32 a;
    asm("{ .reg .u64 t; cvta.to.shared.u64 t, %1; cvt.u32.u64 %0, t; }" : "=r"(a) : "l"(p));
    return a;
}
__device__ __forceinline__ void ldm4(u32& r0, u32& r1, u32& r2, u32& r3, u32 a) {
    asm volatile("ldmatrix.sync.aligned.m8n8.x4.shared.b16 {%0,%1,%2,%3}, [%4];"
                 : "=r"(r0), "=r"(r1), "=r"(r2), "=r"(r3) : "r"(a));
}
__device__ __forceinline__ void mma_f16(float* d, const u32* a, u32 b0, u32 b1) {
    asm volatile(
        "mma.sync.aligned.m16n8k16.row.col.f32.f16.f16.f32 "
        "{%0,%1,%2,%3}, {%4,%5,%6,%7}, {%8,%9}, {%0,%1,%2,%3};"
        : "+f"(d[0]), "+f"(d[1]), "+f"(d[2]), "+f"(d[3])
        : "r"(a[0]), "r"(a[1]), "r"(a[2]), "r"(a[3]), "r"(b0), "r"(b1));
}
__device__ __forceinline__ u32 pkh2(float x, float y) {
    __half2 h = __floats2half2_rn(x, y);
    return *(u32*)&h;
}
// split float4 -> packed fp16 hi (2x u32) and fp16 lo residual (2x u32)
__device__ __forceinline__ void split4h(float4 v, uint2& h, uint2& l) {
    float hx = __half2float(__float2half_rn(v.x));
    float hy = __half2float(__float2half_rn(v.y));
    float hz = __half2float(__float2half_rn(v.z));
    float hw = __half2float(__float2half_rn(v.w));
    h.x = pkh2(v.x, v.y);            h.y = pkh2(v.z, v.w);
    l.x = pkh2(v.x - hx, v.y - hy);  l.y = pkh2(v.z - hz, v.w - hw);
}

// ---------------- preprocessing ----------------
// Edge convert + degree histogram. Per-thread dtype detect: reference says
// int64 but JAX w/o x64 emits int32; an int64 view of int32 data is >= NN
// almost surely (8 broadcast loads, L1-resident).
__global__ void convert_hist_kernel(const void* __restrict__ eptr) {
    int i = blockIdx.x * blockDim.x + threadIdx.x;
    if (i >= EE) return;
    const unsigned long long* e64 = (const unsigned long long*)eptr;
    bool is64 = true;
    #pragma unroll
    for (int t = 0; t < 8; t++)
        is64 &= (e64[t] < (unsigned long long)NN);
    int s, d;
    if (is64) {
        const long long* e = (const long long*)eptr;
        s = (int)e[i]; d = (int)e[EE + i];
    } else {
        const int* e = (const int*)eptr;
        s = e[i]; d = e[EE + i];
    }
    g_src[i] = s;
    g_dst[i] = d;
    atomicAdd(&g_count[d], 1);
}

// multi-block scan: (1) per-block exclusive scan + block totals
__global__ void scan1_kernel() {
    __shared__ int wsum[32];
    int tid = threadIdx.x;
    int lane = tid & 31, wid = tid >> 5;
    int idx = blockIdx.x * 1024 + tid;
    int v = (idx < NN) ? g_count[idx] : 0;
    int s = v;
    #pragma unroll
    for (int o = 1; o < 32; o <<= 1) {
        int t = __shfl_up_sync(0xffffffffu, s, o);
        if (lane >= o) s += t;
    }
    if (lane == 31) wsum[wid] = s;
    __syncthreads();
    if (wid == 0) {
        int w = wsum[lane];
        #pragma unroll
        for (int o = 1; o < 32; o <<= 1) {
            int t = __shfl_up_sync(0xffffffffu, w, o);
            if (lane >= o) w += t;
        }
        wsum[lane] = w;
    }
    __syncthreads();
    int incl = s + ((wid > 0) ? wsum[wid - 1] : 0);
    if (idx < NN) g_rowptr[idx] = incl - v;          // block-local exclusive
    if (tid == 1023) g_btot[blockIdx.x] = incl;      // block total
}

// (2) scan the block totals
__global__ void scan2_kernel() {
    __shared__ int w0;
    int tid = threadIdx.x;
    int lane = tid & 31, wid = tid >> 5;
    int v = (tid < SCAN_BLKS) ? g_btot[tid] : 0;
    int s = v;
    #pragma unroll
    for (int o = 1; o < 32; o <<= 1) {
        int t = __shfl_up_sync(0xffffffffu, s, o);
        if (lane >= o) s += t;
    }
    if (wid == 0 && lane == 31) w0 = s;
    __syncthreads();
    int incl = s + (wid ? w0 : 0);
    if (tid < SCAN_BLKS) g_boff[tid] = incl - v;
    if (tid == 63) g_rowptr[NN] = incl;
}

// (3) apply block offsets; emit cursor + inv-degree
__global__ void scan3_kernel() {
    int idx = blockIdx.x * 1024 + threadIdx.x;
    if (idx >= NN) return;
    int r = g_rowptr[idx] + g_boff[blockIdx.x];
    g_rowptr[idx] = r;
    g_cursor[idx] = r;
    g_invdeg[idx] = 1.0f / (float)max(g_count[idx], 1);
}

__global__ void fill_kernel() {
    int i = blockIdx.x * blockDim.x + threadIdx.x;
    if (i >= EE) return;
    int d = g_dst[i];
    int p = atomicAdd(&g_cursor[d], 1);
    g_col[p] = g_src[i];
}

// Warp-per-node rank sort of each adjacency list (coalesced loads, 32 shuffle
// compares). Output = ascending values regardless of the nondeterministic
// atomic fill order -> deterministic summation order. Deg>32 fallback: lane-0
// insertion sort (Poisson(12) tail, essentially never). Also re-zeroes g_count
// for the NEXT call's histogram.
__global__ void sortnb_kernel() {
    int node = (blockIdx.x * blockDim.x + threadIdx.x) >> 5;
    if (node >= NN) return;
    int lane = threadIdx.x & 31;
    int b = g_rowptr[node], e = g_rowptr[node + 1];
    int deg = e - b;
    if (deg > 1) {
        if (deg <= 32) {
            int v = (lane < deg) ? g_col[b + lane] : 0x7fffffff;
            int rank = 0;
            #pragma unroll
            for (int m = 0; m < 32; m++) {
                int vm = __shfl_sync(0xffffffffu, v, m);
                rank += (m < deg) && ((vm < v) || (vm == v && m < lane));
            }
            __syncwarp();
            if (lane < deg) g_col[b + rank] = v;
        } else if (lane == 0) {
            for (int i = b + 1; i < e; i++) {
                int v = g_col[i];
                int j = i - 1;
                while (j >= b && g_col[j] > v) { g_col[j + 1] = g_col[j]; j--; }
                g_col[j + 1] = v;
            }
        }
    }
    if (lane == 0) g_count[node] = 0;
}

// ---------------- aggregation ----------------
// One warp per node; lane owns a float4. 25.6 MB table is L2-resident.
__global__ void aggregate_kernel(const float* __restrict__ hin, float* __restrict__ mean) {
    int node = (blockIdx.x * blockDim.x + threadIdx.x) >> 5;
    if (node >= NN) return;
    int lane = threadIdx.x & 31;
    int j = g_rowptr[node], end = g_rowptr[node + 1];
    const float4* p = (const float4*)hin;
    float4 acc = make_float4(0.f, 0.f, 0.f, 0.f);
    for (; j + 2 <= end; j += 2) {
        int s0 = g_col[j], s1 = g_col[j + 1];
        float4 v0 = p[s0 * 32 + lane];
        float4 v1 = p[s1 * 32 + lane];
        acc.x += v0.x; acc.y += v0.y; acc.z += v0.z; acc.w += v0.w;
        acc.x += v1.x; acc.y += v1.y; acc.z += v1.z; acc.w += v1.w;
    }
    if (j < end) {
        float4 v = p[g_col[j] * 32 + lane];
        acc.x += v.x; acc.y += v.y; acc.z += v.z; acc.w += v.w;
    }
    float id = g_invdeg[node];
    acc.x *= id; acc.y *= id; acc.z *= id; acc.w *= id;
    *((float4*)mean + node * 32 + lane) = acc;
}

// ---------------- fp16x2 mma.sync GEMM ----------------
// out = relu([mean|h] @ [Wl;Wr]^T + bl) as one K=256 GEMM.
// W in plain fp16 (uniform weights in [-1/sqrt(128),1/sqrt(128)] round to fp16
// with ~1.2e-4 relative error); A split fp16 hi + fp16 lo residual (2^-22).
// 2 MMAs per k-step. 148 persistent CTAs x 512 thr; warp tile 32x32; A chunks
// (128 rows x 64 k) double-buffered with gmem prefetch before mma.
__global__ __launch_bounds__(512, 1)
void gemm_mma_kernel(const float* __restrict__ mean, const float* __restrict__ hin,
                     const float* __restrict__ Wl, const float* __restrict__ bl,
                     const float* __restrict__ Wr, float* __restrict__ out)
{
    extern __shared__ char smem[];
    const u32 sb = smem_u32(smem);
    const int tid = threadIdx.x;
    const int w = tid >> 5;
    const int lane = tid & 31;

    // ---- stage W fp16: Wcat[n][k] (k<128: Wl, else Wr), rows 512B, SWW swizzle ----
    for (int s = tid; s < 128 * 64; s += 512) {
        int n = s >> 6, k4 = s & 63;
        int k = k4 * 4;
        float4 v = (k < 128) ? *(const float4*)(Wl + n * 128 + k)
                             : *(const float4*)(Wr + n * 128 + (k - 128));
        uint2 h;
        h.x = pkh2(v.x, v.y);
        h.y = pkh2(v.z, v.w);
        *(uint2*)(smem + SM_WH + SWW(n * 512 + k4 * 8)) = h;
    }

    // warp grid: 4 row groups x 4 col groups
    const int wr = (w & 3) * 32;           // warp row base in tile
    const int wc = (w >> 2) * 32;          // warp col base
    const u32 a_lane = (u32)((lane & 15) * 128 + ((lane >> 4) & 1) * 16);
    const u32 b_lane = (u32)(((lane & 7) + ((lane >> 4) & 1) * 8) * 512 + ((lane >> 3) & 1) * 16);

    // bias regs for this thread's columns
    float2 brg[4];
    #pragma unroll
    for (int ni = 0; ni < 4; ni++)
        brg[ni] = *(const float2*)(bl + wc + ni * 8 + (lane & 3) * 2);

    __syncthreads();

    for (int tix = blockIdx.x; tix < NTILES; tix += GRID_GEMM) {
        const int row0 = tix * 128;
        float acc[8][4];
        #pragma unroll
        for (int i = 0; i < 8; i++)
            #pragma unroll
            for (int q = 0; q < 4; q++) acc[i][q] = 0.f;

        // stage chunk 0 into buf 0
        float4 v[4];
        {
            #pragma unroll
            for (int j = 0; j < 4; j++) {
                int s = tid + j * 512;
                int row = s >> 4, k4 = s & 15;
                int gr = row0 + row;
                v[j] = make_float4(0.f, 0.f, 0.f, 0.f);
                if (gr < NN) v[j] = *(const float4*)(mean + gr * 128 + k4 * 4);
            }
            #pragma unroll
            for (int j = 0; j < 4; j++) {
                int s = tid + j * 512;
                int row = s >> 4, k4 = s & 15;
                uint2 h, l;
                split4h(v[j], h, l);
                u32 off = SWA(row * 128 + k4 * 8);
                *(uint2*)(smem + SM_AB + off) = h;
                *(uint2*)(smem + SM_AB + 16384 + off) = l;
            }
        }
        __syncthreads();

        for (int kc = 0; kc < 4; kc++) {
            const int buf = kc & 1;

            // prefetch next chunk's gmem into regs (hidden behind mma)
            if (kc < 3) {
                const float* src = (kc + 1 < 2) ? mean : hin;
                int kbase = ((kc + 1) & 1) * 64;
                #pragma unroll
                for (int j = 0; j < 4; j++) {
                    int s = tid + j * 512;
                    int row = s >> 4, k4 = s & 15;
                    int gr = row0 + row;
                    v[j] = make_float4(0.f, 0.f, 0.f, 0.f);
                    if (gr < NN) v[j] = *(const float4*)(src + gr * 128 + kbase + k4 * 4);
                }
            }

            // ---- mma over 4 k16 steps, 2 split terms ----
            const u32 AH = sb + SM_AB + buf * 32768;
            const u32 AL = AH + 16384;
            const u32 BH = sb + SM_WH;
            #pragma unroll
            for (int ks = 0; ks < 4; ks++) {
                u32 ah[2][4], al[2][4], bh[2][4];
                u32 aoff = (u32)(wr * 128) + (u32)(ks * 32) + a_lane;
                #pragma unroll
                for (int mi = 0; mi < 2; mi++) {
                    ldm4(ah[mi][0], ah[mi][1], ah[mi][2], ah[mi][3],
                         AH + SWA(aoff + mi * 16 * 128));
                    ldm4(al[mi][0], al[mi][1], al[mi][2], al[mi][3],
                         AL + SWA(aoff + mi * 16 * 128));
                }
                u32 boff = (u32)(wc * 512) + (u32)((kc * 8 + ks * 2) * 16) + b_lane;
                #pragma unroll
                for (int g = 0; g < 2; g++)
                    ldm4(bh[g][0], bh[g][1], bh[g][2], bh[g][3],
                         BH + SWW(boff + g * 16 * 512));
                // hi*w
                #pragma unroll
                for (int mi = 0; mi < 2; mi++)
                    #pragma unroll
                    for (int ni = 0; ni < 4; ni++)
                        mma_f16(acc[mi * 4 + ni], ah[mi],
                                bh[ni >> 1][(ni & 1) * 2], bh[ni >> 1][(ni & 1) * 2 + 1]);
                // lo*w
                #pragma unroll
                for (int mi = 0; mi < 2; mi++)
                    #pragma unroll
                    for (int ni = 0; ni < 4; ni++)
                        mma_f16(acc[mi * 4 + ni], al[mi],
                                bh[ni >> 1][(ni & 1) * 2], bh[ni >> 1][(ni & 1) * 2 + 1]);
            }

            // store prefetched chunk into other buffer
            if (kc < 3) {
                int nb = buf ^ 1;
                #pragma unroll
                for (int j = 0; j < 4; j++) {
                    int s = tid + j * 512;
                    int row = s >> 4, k4 = s & 15;
                    uint2 h, l;
                    split4h(v[j], h, l);
                    u32 off = SWA(row * 128 + k4 * 8);
                    *(uint2*)(smem + SM_AB + nb * 32768 + off) = h;
                    *(uint2*)(smem + SM_AB + nb * 32768 + 16384 + off) = l;
                }
            }
            __syncthreads();
        }

        // ---- epilogue: bias + relu + direct STG ----
        #pragma unroll
        for (int mi = 0; mi < 2; mi++) {
            int r0 = row0 + wr + mi * 16 + (lane >> 2);
            #pragma unroll
            for (int ni = 0; ni < 4; ni++) {
                const float* d = acc[mi * 4 + ni];
                int c = wc + ni * 8 + (lane & 3) * 2;
                if (r0 < NN) {
                    float2 o;
                    o.x = fmaxf(d[0] + brg[ni].x, 0.f);
                    o.y = fmaxf(d[1] + brg[ni].y, 0.f);
                    *(float2*)(out + (long)r0 * 128 + c) = o;
                }
                if (r0 + 8 < NN) {
                    float2 o;
                    o.x = fmaxf(d[2] + brg[ni].x, 0.f);
                    o.y = fmaxf(d[3] + brg[ni].y, 0.f);
                    *(float2*)(out + (long)(r0 + 8) * 128 + c) = o;
                }
            }
        }
        __syncthreads();   // tile done before next chunk0 staging overwrites buf0
    }
}

// ---------------- launch ----------------
extern "C" void kernel_launch(void* const* d_in, const int* in_sizes, int n_in,
                              void* d_out, int out_size) {
    const float* x   = (const float*)d_in[0];
    const void*  ei  = d_in[1];
    const float* Wl1 = (const float*)d_in[2];
    const float* bl1 = (const float*)d_in[3];
    const float* Wr1 = (const float*)d_in[4];
    const float* Wl2 = (const float*)d_in[5];
    const float* bl2 = (const float*)d_in[6];
    const float* Wr2 = (const float*)d_in[7];
    const float* Wl3 = (const float*)d_in[8];
    const float* bl3 = (const float*)d_in[9];
    const float* Wr3 = (const float*)d_in[10];
    float* out = (float*)d_out;

    cudaFuncSetAttribute(gemm_mma_kernel, cudaFuncAttributeMaxDynamicSharedMemorySize, GEMM_SMEM);

    float *pA, *pB, *pM;
    cudaGetSymbolAddress((void**)&pA, g_bufA);
    cudaGetSymbolAddress((void**)&pB, g_bufB);
    cudaGetSymbolAddress((void**)&pM, g_mean);

    // ---- graph preprocessing (6 launches; deterministic every call) ----
    convert_hist_kernel<<<(EE + 255) / 256, 256>>>(ei);
    scan1_kernel<<<SCAN_BLKS, 1024>>>();
    scan2_kernel<<<1, 64>>>();
    scan3_kernel<<<SCAN_BLKS, 1024>>>();
    fill_kernel<<<(EE + 255) / 256, 256>>>();
    sortnb_kernel<<<(NN * 32 + 255) / 256, 256>>>();   // warp per node

    const int agg_blocks = (NN * 32 + 255) / 256;

    // ---- layer 1 ----
    aggregate_kernel<<<agg_blocks, 256>>>(x, pM);
    gemm_mma_kernel<<<GRID_GEMM, 512, GEMM_SMEM>>>(pM, x, Wl1, bl1, Wr1, pA);
    // ---- layer 2 ----
    aggregate_kernel<<<agg_blocks, 256>>>(pA, pM);
    gemm_mma_kernel<<<GRID_GEMM, 512, GEMM_SMEM>>>(pM, pA, Wl2, bl2, Wr2, pB);
    // ---- layer 3 ----
    aggregate_kernel<<<agg_blocks, 256>>>(pB, pM);
    gemm_mma_kernel<<<GRID_GEMM, 512, GEMM_SMEM>>>(pM, pB, Wl3, bl3, Wr3, out);
}